// round 1
// baseline (speedup 1.0000x reference)
#include <cuda_runtime.h>
#include <cstdint>

// Fused tiny-MLP over B=4.19M rows:
//   h = x@We + be ; n = LN(h)*g1+b1 ; m = relu(n@W1+c1)@W2+c2 ; h += m
//   n = LN(h)*gh+bh ; out = n@Wh+ch
// Strategy: 2 rows per thread packed into f32x2 lanes; all weights held in
// shared memory pre-duplicated as (w,w) u64 so one LDS.64 feeds one fma.rn.f32x2.

#define D_IN 10
#define D    12
#define EPS  1e-5f
#define THREADS 256

typedef unsigned long long u64;

__device__ __forceinline__ u64 pk(float lo, float hi) {
    u64 r; asm("mov.b64 %0, {%1,%2};" : "=l"(r) : "f"(lo), "f"(hi)); return r;
}
__device__ __forceinline__ void upk(u64 v, float& lo, float& hi) {
    asm("mov.b64 {%0,%1}, %2;" : "=f"(lo), "=f"(hi) : "l"(v));
}
__device__ __forceinline__ u64 fma2(u64 a, u64 b, u64 c) {
    u64 d; asm("fma.rn.f32x2 %0, %1, %2, %3;" : "=l"(d) : "l"(a), "l"(b), "l"(c)); return d;
}
__device__ __forceinline__ u64 add2(u64 a, u64 b) {
    u64 d; asm("add.rn.f32x2 %0, %1, %2;" : "=l"(d) : "l"(a), "l"(b)); return d;
}
__device__ __forceinline__ u64 mul2(u64 a, u64 b) {
    u64 d; asm("mul.rn.f32x2 %0, %1, %2;" : "=l"(d) : "l"(a), "l"(b)); return d;
}

// shared weight layout offsets (in u64 elements)
#define OFF_WE   0            // 120
#define OFF_BE   120          // 12
#define OFF_G1   132          // 12
#define OFF_B1   144          // 12
#define OFF_W1   156          // 144
#define OFF_C1   300          // 12
#define OFF_W2   312          // 144
#define OFF_C2   456          // 12
#define OFF_GH   468          // 12
#define OFF_BH   480          // 12
#define OFF_WH   492          // 144
#define OFF_CH   636          // 12
#define W_TOTAL  648

__global__ __launch_bounds__(THREADS)
void fused_mlp_kernel(const float* __restrict__ x,
                      const float* __restrict__ w_embed,
                      const float* __restrict__ b_embed,
                      const float* __restrict__ g1,
                      const float* __restrict__ b1,
                      const float* __restrict__ w_fc1,
                      const float* __restrict__ c_fc1,
                      const float* __restrict__ w_fc2,
                      const float* __restrict__ c_fc2,
                      const float* __restrict__ gh,
                      const float* __restrict__ bh,
                      const float* __restrict__ w_head,
                      const float* __restrict__ c_head,
                      float* __restrict__ out,
                      int n_pairs)
{
    __shared__ u64 sW[W_TOTAL];

    // cooperative load of all weights, duplicated into both f32x2 halves
    for (int i = threadIdx.x; i < W_TOTAL; i += THREADS) {
        float v;
        if      (i < OFF_BE)  v = w_embed[i - OFF_WE];
        else if (i < OFF_G1)  v = b_embed[i - OFF_BE];
        else if (i < OFF_B1)  v = g1[i - OFF_G1];
        else if (i < OFF_W1)  v = b1[i - OFF_B1];
        else if (i < OFF_C1)  v = w_fc1[i - OFF_W1];
        else if (i < OFF_W2)  v = c_fc1[i - OFF_C1];
        else if (i < OFF_C2)  v = w_fc2[i - OFF_W2];
        else if (i < OFF_GH)  v = c_fc2[i - OFF_C2];
        else if (i < OFF_BH)  v = gh[i - OFF_GH];
        else if (i < OFF_WH)  v = bh[i - OFF_BH];
        else if (i < OFF_CH)  v = w_head[i - OFF_WH];
        else                  v = c_head[i - OFF_CH];
        sW[i] = pk(v, v);
    }
    __syncthreads();

    int gid = blockIdx.x * THREADS + threadIdx.x;
    if (gid >= n_pairs) return;

    // ---- load two rows of x (20 floats, 16B-aligned: 20*4*gid % 16 == 0) ----
    float xf[2 * D_IN];
    const float4* xv = reinterpret_cast<const float4*>(x + (size_t)gid * (2 * D_IN));
    #pragma unroll
    for (int i = 0; i < 5; i++) reinterpret_cast<float4*>(xf)[i] = xv[i];

    u64 x2[D_IN];
    #pragma unroll
    for (int i = 0; i < D_IN; i++) x2[i] = pk(xf[i], xf[D_IN + i]);

    const u64 inv_d  = pk(1.0f / D, 1.0f / D);
    const u64 ninv_d = pk(-1.0f / D, -1.0f / D);
    const u64 eps2   = pk(EPS, EPS);

    // ---- embed: h = x @ We + be ----
    u64 h[D];
    #pragma unroll
    for (int j = 0; j < D; j++) h[j] = sW[OFF_BE + j];
    #pragma unroll
    for (int i = 0; i < D_IN; i++) {
        #pragma unroll
        for (int j = 0; j < D; j++)
            h[j] = fma2(x2[i], sW[OFF_WE + i * D + j], h[j]);
    }

    u64 n[D], t[D];

    // ---- LN1 ----
    {
        u64 s = h[0];
        #pragma unroll
        for (int j = 1; j < D; j++) s = add2(s, h[j]);
        u64 negmu = mul2(s, ninv_d);
        u64 v = 0ull; // bits(0,0) == (0.0f, 0.0f)
        #pragma unroll
        for (int j = 0; j < D; j++) {
            t[j] = add2(h[j], negmu);     // centered
            v = fma2(t[j], t[j], v);
        }
        u64 var = add2(mul2(v, inv_d), eps2);
        float a, b; upk(var, a, b);
        u64 inv = pk(rsqrtf(a), rsqrtf(b));
        #pragma unroll
        for (int j = 0; j < D; j++)
            n[j] = fma2(mul2(t[j], inv), sW[OFF_G1 + j], sW[OFF_B1 + j]);
    }

    // ---- fc1 + relu ----
    #pragma unroll
    for (int j = 0; j < D; j++) t[j] = sW[OFF_C1 + j];
    #pragma unroll
    for (int i = 0; i < D; i++) {
        #pragma unroll
        for (int j = 0; j < D; j++)
            t[j] = fma2(n[i], sW[OFF_W1 + i * D + j], t[j]);
    }
    #pragma unroll
    for (int j = 0; j < D; j++) {
        float a, b; upk(t[j], a, b);
        t[j] = pk(fmaxf(a, 0.0f), fmaxf(b, 0.0f));
    }

    // ---- fc2 + residual ----
    #pragma unroll
    for (int j = 0; j < D; j++) n[j] = sW[OFF_C2 + j];
    #pragma unroll
    for (int i = 0; i < D; i++) {
        #pragma unroll
        for (int j = 0; j < D; j++)
            n[j] = fma2(t[i], sW[OFF_W2 + i * D + j], n[j]);
    }
    #pragma unroll
    for (int j = 0; j < D; j++) h[j] = add2(h[j], n[j]);

    // ---- LN-head ----
    {
        u64 s = h[0];
        #pragma unroll
        for (int j = 1; j < D; j++) s = add2(s, h[j]);
        u64 negmu = mul2(s, ninv_d);
        u64 v = 0ull;
        #pragma unroll
        for (int j = 0; j < D; j++) {
            t[j] = add2(h[j], negmu);
            v = fma2(t[j], t[j], v);
        }
        u64 var = add2(mul2(v, inv_d), eps2);
        float a, b; upk(var, a, b);
        u64 inv = pk(rsqrtf(a), rsqrtf(b));
        #pragma unroll
        for (int j = 0; j < D; j++)
            n[j] = fma2(mul2(t[j], inv), sW[OFF_GH + j], sW[OFF_BH + j]);
    }

    // ---- head: out = n @ Wh + ch ----
    #pragma unroll
    for (int j = 0; j < D; j++) t[j] = sW[OFF_CH + j];
    #pragma unroll
    for (int i = 0; i < D; i++) {
        #pragma unroll
        for (int j = 0; j < D; j++)
            t[j] = fma2(n[i], sW[OFF_WH + i * D + j], t[j]);
    }

    // ---- store two rows (24 floats, 16B-aligned: 24*4*gid % 16 == 0) ----
    float of[2 * D];
    #pragma unroll
    for (int j = 0; j < D; j++) upk(t[j], of[j], of[D + j]);
    float4* ov = reinterpret_cast<float4*>(out + (size_t)gid * (2 * D));
    #pragma unroll
    for (int i = 0; i < 6; i++) ov[i] = reinterpret_cast<float4*>(of)[i];
}

extern "C" void kernel_launch(void* const* d_in, const int* in_sizes, int n_in,
                              void* d_out, int out_size)
{
    const float* x       = (const float*)d_in[0];
    const float* w_embed = (const float*)d_in[1];
    const float* b_embed = (const float*)d_in[2];
    const float* g1      = (const float*)d_in[3];
    const float* b1      = (const float*)d_in[4];
    const float* w_fc1   = (const float*)d_in[5];
    const float* c_fc1   = (const float*)d_in[6];
    const float* w_fc2   = (const float*)d_in[7];
    const float* c_fc2   = (const float*)d_in[8];
    const float* gh      = (const float*)d_in[9];
    const float* bh      = (const float*)d_in[10];
    const float* w_head  = (const float*)d_in[11];
    const float* c_head  = (const float*)d_in[12];
    float* out = (float*)d_out;

    int rows    = in_sizes[0] / D_IN;   // 4194304
    int n_pairs = rows / 2;             // even B guaranteed by shape
    int blocks  = (n_pairs + THREADS - 1) / THREADS;

    fused_mlp_kernel<<<blocks, THREADS>>>(x, w_embed, b_embed, g1, b1,
                                          w_fc1, c_fc1, w_fc2, c_fc2,
                                          gh, bh, w_head, c_head,
                                          out, n_pairs);
}

// round 3
// speedup vs baseline: 1.0854x; 1.0854x over previous
#include <cuda_runtime.h>
#include <cstdint>

// Fused tiny-MLP, B=4.19M rows, fp32.
// R3 (= R2 resubmit after infra failure): 4 rows/thread (two f32x2 pair-sets
// sharing every weight fetch) and LDS.128 weight loads (two duplicated-u64
// weights per load). 4x fewer shared-mem wavefronts than R1 (L1-bound at 85%).

#define D_IN 10
#define D    12
#define EPS  1e-5f
#define THREADS 128

typedef unsigned long long u64;

__device__ __forceinline__ u64 pk(float lo, float hi) {
    u64 r; asm("mov.b64 %0, {%1,%2};" : "=l"(r) : "f"(lo), "f"(hi)); return r;
}
__device__ __forceinline__ void upk(u64 v, float& lo, float& hi) {
    asm("mov.b64 {%0,%1}, %2;" : "=f"(lo), "=f"(hi) : "l"(v));
}
__device__ __forceinline__ u64 fma2(u64 a, u64 b, u64 c) {
    u64 d; asm("fma.rn.f32x2 %0, %1, %2, %3;" : "=l"(d) : "l"(a), "l"(b), "l"(c)); return d;
}
__device__ __forceinline__ u64 add2(u64 a, u64 b) {
    u64 d; asm("add.rn.f32x2 %0, %1, %2;" : "=l"(d) : "l"(a), "l"(b)); return d;
}
__device__ __forceinline__ u64 mul2(u64 a, u64 b) {
    u64 d; asm("mul.rn.f32x2 %0, %1, %2;" : "=l"(d) : "l"(a), "l"(b)); return d;
}

// shared layout (u64 elements); ALL offsets even -> 16B-aligned for LDS.128
#define OFF_WE   0            // 120
#define OFF_BE   120          // 12
#define OFF_G1   132          // 12
#define OFF_B1   144          // 12
#define OFF_W1   156          // 144
#define OFF_C1   300          // 12
#define OFF_W2   312          // 144
#define OFF_C2   456          // 12
#define OFF_GH   468          // 12
#define OFF_BH   480          // 12
#define OFF_WH   492          // 144
#define OFF_CH   636          // 12
#define W_TOTAL  648

__global__ __launch_bounds__(THREADS)
void fused_mlp_kernel(const float* __restrict__ x,
                      const float* __restrict__ w_embed,
                      const float* __restrict__ b_embed,
                      const float* __restrict__ g1,
                      const float* __restrict__ b1,
                      const float* __restrict__ w_fc1,
                      const float* __restrict__ c_fc1,
                      const float* __restrict__ w_fc2,
                      const float* __restrict__ c_fc2,
                      const float* __restrict__ gh,
                      const float* __restrict__ bh,
                      const float* __restrict__ w_head,
                      const float* __restrict__ c_head,
                      float* __restrict__ out,
                      int n_quads)
{
    __shared__ alignas(16) u64 sW[W_TOTAL];

    for (int i = threadIdx.x; i < W_TOTAL; i += THREADS) {
        float v;
        if      (i < OFF_BE)  v = w_embed[i - OFF_WE];
        else if (i < OFF_G1)  v = b_embed[i - OFF_BE];
        else if (i < OFF_B1)  v = g1[i - OFF_G1];
        else if (i < OFF_W1)  v = b1[i - OFF_B1];
        else if (i < OFF_C1)  v = w_fc1[i - OFF_W1];
        else if (i < OFF_W2)  v = c_fc1[i - OFF_C1];
        else if (i < OFF_C2)  v = w_fc2[i - OFF_W2];
        else if (i < OFF_GH)  v = c_fc2[i - OFF_C2];
        else if (i < OFF_BH)  v = gh[i - OFF_GH];
        else if (i < OFF_WH)  v = bh[i - OFF_BH];
        else if (i < OFF_CH)  v = w_head[i - OFF_WH];
        else                  v = c_head[i - OFF_CH];
        sW[i] = pk(v, v);
    }
    __syncthreads();

    int gid = blockIdx.x * THREADS + threadIdx.x;
    if (gid >= n_quads) return;

    // ---- load 4 rows of x: 40 floats, 16B-aligned (160B * gid) ----
    float xf[4 * D_IN];
    const float4* xv = reinterpret_cast<const float4*>(x + (size_t)gid * (4 * D_IN));
    #pragma unroll
    for (int i = 0; i < 10; i++) reinterpret_cast<float4*>(xf)[i] = xv[i];

    u64 xa[D_IN], xb[D_IN];
    #pragma unroll
    for (int i = 0; i < D_IN; i++) {
        xa[i] = pk(xf[i],          xf[D_IN + i]);       // rows 0,1
        xb[i] = pk(xf[2*D_IN + i], xf[3*D_IN + i]);     // rows 2,3
    }

    const u64 inv_d  = pk(1.0f / D, 1.0f / D);
    const u64 ninv_d = pk(-1.0f / D, -1.0f / D);
    const u64 eps2   = pk(EPS, EPS);

    const ulonglong2* sW2 = reinterpret_cast<const ulonglong2*>(sW);
    #define LD2(off) sW2[(off) >> 1]

    // ---- embed ----
    u64 ha[D], hb[D];
    #pragma unroll
    for (int j = 0; j < D; j += 2) {
        ulonglong2 b = LD2(OFF_BE + j);
        ha[j] = b.x; ha[j+1] = b.y; hb[j] = b.x; hb[j+1] = b.y;
    }
    #pragma unroll
    for (int i = 0; i < D_IN; i++) {
        #pragma unroll
        for (int j = 0; j < D; j += 2) {
            ulonglong2 w = LD2(OFF_WE + i * D + j);
            ha[j]   = fma2(xa[i], w.x, ha[j]);
            hb[j]   = fma2(xb[i], w.x, hb[j]);
            ha[j+1] = fma2(xa[i], w.y, ha[j+1]);
            hb[j+1] = fma2(xb[i], w.y, hb[j+1]);
        }
    }

    u64 na[D], nb[D], ta[D], tb[D];

    // ---- LN1 (both sets) ----
    {
        u64 sa = ha[0], sb = hb[0];
        #pragma unroll
        for (int j = 1; j < D; j++) { sa = add2(sa, ha[j]); sb = add2(sb, hb[j]); }
        u64 nma = mul2(sa, ninv_d), nmb = mul2(sb, ninv_d);
        u64 va = 0ull, vb = 0ull;
        #pragma unroll
        for (int j = 0; j < D; j++) {
            ta[j] = add2(ha[j], nma); va = fma2(ta[j], ta[j], va);
            tb[j] = add2(hb[j], nmb); vb = fma2(tb[j], tb[j], vb);
        }
        u64 vara = add2(mul2(va, inv_d), eps2);
        u64 varb = add2(mul2(vb, inv_d), eps2);
        float p, q; upk(vara, p, q);
        u64 ia = pk(rsqrtf(p), rsqrtf(q));
        upk(varb, p, q);
        u64 ib = pk(rsqrtf(p), rsqrtf(q));
        #pragma unroll
        for (int j = 0; j < D; j += 2) {
            ulonglong2 g = LD2(OFF_G1 + j);
            ulonglong2 b = LD2(OFF_B1 + j);
            na[j]   = fma2(mul2(ta[j],   ia), g.x, b.x);
            nb[j]   = fma2(mul2(tb[j],   ib), g.x, b.x);
            na[j+1] = fma2(mul2(ta[j+1], ia), g.y, b.y);
            nb[j+1] = fma2(mul2(tb[j+1], ib), g.y, b.y);
        }
    }

    // ---- fc1 + relu ----
    #pragma unroll
    for (int j = 0; j < D; j += 2) {
        ulonglong2 c = LD2(OFF_C1 + j);
        ta[j] = c.x; ta[j+1] = c.y; tb[j] = c.x; tb[j+1] = c.y;
    }
    #pragma unroll
    for (int i = 0; i < D; i++) {
        #pragma unroll
        for (int j = 0; j < D; j += 2) {
            ulonglong2 w = LD2(OFF_W1 + i * D + j);
            ta[j]   = fma2(na[i], w.x, ta[j]);
            tb[j]   = fma2(nb[i], w.x, tb[j]);
            ta[j+1] = fma2(na[i], w.y, ta[j+1]);
            tb[j+1] = fma2(nb[i], w.y, tb[j+1]);
        }
    }
    #pragma unroll
    for (int j = 0; j < D; j++) {
        float p, q;
        upk(ta[j], p, q); ta[j] = pk(fmaxf(p, 0.0f), fmaxf(q, 0.0f));
        upk(tb[j], p, q); tb[j] = pk(fmaxf(p, 0.0f), fmaxf(q, 0.0f));
    }

    // ---- fc2 + residual ----
    #pragma unroll
    for (int j = 0; j < D; j += 2) {
        ulonglong2 c = LD2(OFF_C2 + j);
        na[j] = c.x; na[j+1] = c.y; nb[j] = c.x; nb[j+1] = c.y;
    }
    #pragma unroll
    for (int i = 0; i < D; i++) {
        #pragma unroll
        for (int j = 0; j < D; j += 2) {
            ulonglong2 w = LD2(OFF_W2 + i * D + j);
            na[j]   = fma2(ta[i], w.x, na[j]);
            nb[j]   = fma2(tb[i], w.x, nb[j]);
            na[j+1] = fma2(ta[i], w.y, na[j+1]);
            nb[j+1] = fma2(tb[i], w.y, nb[j+1]);
        }
    }
    #pragma unroll
    for (int j = 0; j < D; j++) { ha[j] = add2(ha[j], na[j]); hb[j] = add2(hb[j], nb[j]); }

    // ---- LN-head ----
    {
        u64 sa = ha[0], sb = hb[0];
        #pragma unroll
        for (int j = 1; j < D; j++) { sa = add2(sa, ha[j]); sb = add2(sb, hb[j]); }
        u64 nma = mul2(sa, ninv_d), nmb = mul2(sb, ninv_d);
        u64 va = 0ull, vb = 0ull;
        #pragma unroll
        for (int j = 0; j < D; j++) {
            ta[j] = add2(ha[j], nma); va = fma2(ta[j], ta[j], va);
            tb[j] = add2(hb[j], nmb); vb = fma2(tb[j], tb[j], vb);
        }
        u64 vara = add2(mul2(va, inv_d), eps2);
        u64 varb = add2(mul2(vb, inv_d), eps2);
        float p, q; upk(vara, p, q);
        u64 ia = pk(rsqrtf(p), rsqrtf(q));
        upk(varb, p, q);
        u64 ib = pk(rsqrtf(p), rsqrtf(q));
        #pragma unroll
        for (int j = 0; j < D; j += 2) {
            ulonglong2 g = LD2(OFF_GH + j);
            ulonglong2 b = LD2(OFF_BH + j);
            na[j]   = fma2(mul2(ta[j],   ia), g.x, b.x);
            nb[j]   = fma2(mul2(tb[j],   ib), g.x, b.x);
            na[j+1] = fma2(mul2(ta[j+1], ia), g.y, b.y);
            nb[j+1] = fma2(mul2(tb[j+1], ib), g.y, b.y);
        }
    }

    // ---- head ----
    #pragma unroll
    for (int j = 0; j < D; j += 2) {
        ulonglong2 c = LD2(OFF_CH + j);
        ta[j] = c.x; ta[j+1] = c.y; tb[j] = c.x; tb[j+1] = c.y;
    }
    #pragma unroll
    for (int i = 0; i < D; i++) {
        #pragma unroll
        for (int j = 0; j < D; j += 2) {
            ulonglong2 w = LD2(OFF_WH + i * D + j);
            ta[j]   = fma2(na[i], w.x, ta[j]);
            tb[j]   = fma2(nb[i], w.x, tb[j]);
            ta[j+1] = fma2(na[i], w.y, ta[j+1]);
            tb[j+1] = fma2(nb[i], w.y, tb[j+1]);
        }
    }

    // ---- store 4 rows: 48 floats, 16B-aligned (192B * gid) ----
    float of[4 * D];
    #pragma unroll
    for (int j = 0; j < D; j++) {
        upk(ta[j], of[j],       of[D + j]);
        upk(tb[j], of[2*D + j], of[3*D + j]);
    }
    float4* ov = reinterpret_cast<float4*>(out + (size_t)gid * (4 * D));
    #pragma unroll
    for (int i = 0; i < 12; i++) ov[i] = reinterpret_cast<float4*>(of)[i];
}

extern "C" void kernel_launch(void* const* d_in, const int* in_sizes, int n_in,
                              void* d_out, int out_size)
{
    const float* x       = (const float*)d_in[0];
    const float* w_embed = (const float*)d_in[1];
    const float* b_embed = (const float*)d_in[2];
    const float* g1      = (const float*)d_in[3];
    const float* b1      = (const float*)d_in[4];
    const float* w_fc1   = (const float*)d_in[5];
    const float* c_fc1   = (const float*)d_in[6];
    const float* w_fc2   = (const float*)d_in[7];
    const float* c_fc2   = (const float*)d_in[8];
    const float* gh      = (const float*)d_in[9];
    const float* bh      = (const float*)d_in[10];
    const float* w_head  = (const float*)d_in[11];
    const float* c_head  = (const float*)d_in[12];
    float* out = (float*)d_out;

    int rows    = in_sizes[0] / D_IN;   // 4194304
    int n_quads = rows / 4;             // B divisible by 4
    int blocks  = (n_quads + THREADS - 1) / THREADS;

    fused_mlp_kernel<<<blocks, THREADS>>>(x, w_embed, b_embed, g1, b1,
                                          w_fc1, c_fc1, w_fc2, c_fc2,
                                          gh, bh, w_head, c_head,
                                          out, n_quads);
}